// round 14
// baseline (speedup 1.0000x reference)
#include <cuda_runtime.h>
#include <cstdint>

#define D 64
#define MAXN 50000
#define MAXR 10

// Scratch (allocation-free rule: __device__ globals)
__device__ __align__(16) float g_W[(MAXR + 1) * D * D];                 // 11 relation matrices (slot R = self-loop)
__device__ __align__(16) float g_xr[(size_t)MAXR * MAXN * D];           // [R, N, D] transformed features (128 MB)

// ---------------------------------------------------------------------------
// K0: basis decomposition  W_r = sum_b w_comp[r,b] * weight[b]  (+ copy self-loop)
// ---------------------------------------------------------------------------
__global__ void k0_compute_W(const float* __restrict__ weight,
                             const float* __restrict__ w_comp,
                             const float* __restrict__ self_w,
                             int R, int B) {
    int r = blockIdx.x;
    if (r < R) {
        for (int idx = threadIdx.x; idx < D * D; idx += blockDim.x) {
            float acc = 0.f;
            for (int b = 0; b < B; b++)
                acc += w_comp[r * B + b] * weight[b * D * D + idx];
            g_W[r * D * D + idx] = acc;
        }
    } else {
        for (int idx = threadIdx.x; idx < D * D; idx += blockDim.x)
            g_W[r * D * D + idx] = self_w[idx];
    }
}

// ---------------------------------------------------------------------------
// K1: xr[r] = feat @ W_r  (r < R -> g_xr), self-loop (r == R) -> d_out (init)
// Tile: 128 nodes x 64 outs per block, 256 threads, thread tile 8x4,
// inner products via packed fma.rn.f32x2 (2 FLOPs per FMA-pipe issue).
// ---------------------------------------------------------------------------
__global__ __launch_bounds__(256) void k1_gemm(const float* __restrict__ feat,
                                               float* __restrict__ out,
                                               int N, int R) {
    __shared__ __align__(16) float W_s[D][D];        // [k][j]
    __shared__ __align__(16) float feat_s[D][128];   // [k][n] (transposed tile)

    const int r    = blockIdx.y;
    const int base = blockIdx.x * 128;
    const int t    = threadIdx.x;

    // Load W_r (16 KB) into smem
    const float4* Wg = (const float4*)(g_W + r * D * D);
    #pragma unroll
    for (int i = t; i < D * D / 4; i += 256)
        ((float4*)W_s)[i] = Wg[i];

    // Load 128x64 feat tile, transposed into smem (zero-pad tail tile)
    #pragma unroll
    for (int i = 0; i < 8; i++) {
        int idx = t + i * 256;          // 0..2047 float4s
        int nl  = idx >> 4;             // node within tile 0..127
        int k4  = (idx & 15) * 4;       // k offset
        float4 v = make_float4(0.f, 0.f, 0.f, 0.f);
        int n = base + nl;
        if (n < N) v = *(const float4*)(feat + (size_t)n * D + k4);
        feat_s[k4 + 0][nl] = v.x;
        feat_s[k4 + 1][nl] = v.y;
        feat_s[k4 + 2][nl] = v.z;
        feat_s[k4 + 3][nl] = v.w;
    }
    __syncthreads();

    const int tx = t & 15, ty = t >> 4;
    const int j0 = tx * 4;      // 4 output columns (2 f32x2 pairs)
    const int n0 = ty * 8;      // 8 nodes

    unsigned long long c[8][2];
    #pragma unroll
    for (int i = 0; i < 8; i++) { c[i][0] = 0ull; c[i][1] = 0ull; }

    #pragma unroll 8
    for (int k = 0; k < D; k++) {
        float4 b4 = *(const float4*)&W_s[k][j0];
        unsigned long long b01, b23;
        asm("mov.b64 %0,{%1,%2};" : "=l"(b01) : "f"(b4.x), "f"(b4.y));
        asm("mov.b64 %0,{%1,%2};" : "=l"(b23) : "f"(b4.z), "f"(b4.w));
        float4 a0 = *(const float4*)&feat_s[k][n0];
        float4 a1 = *(const float4*)&feat_s[k][n0 + 4];
        float av[8] = {a0.x, a0.y, a0.z, a0.w, a1.x, a1.y, a1.z, a1.w};
        #pragma unroll
        for (int i = 0; i < 8; i++) {
            unsigned long long a2;
            asm("mov.b64 %0,{%1,%1};" : "=l"(a2) : "f"(av[i]));
            asm("fma.rn.f32x2 %0, %1, %2, %0;" : "+l"(c[i][0]) : "l"(a2), "l"(b01));
            asm("fma.rn.f32x2 %0, %1, %2, %0;" : "+l"(c[i][1]) : "l"(a2), "l"(b23));
        }
    }

    float* dstbase = (r < R) ? (g_xr + (size_t)r * N * D) : out;
    #pragma unroll
    for (int i = 0; i < 8; i++) {
        int n = base + n0 + i;
        if (n < N) {
            float x, y, z, w;
            asm("mov.b64 {%0,%1},%2;" : "=f"(x), "=f"(y) : "l"(c[i][0]));
            asm("mov.b64 {%0,%1},%2;" : "=f"(z), "=f"(w) : "l"(c[i][1]));
            *(float4*)(dstbase + (size_t)n * D + j0) = make_float4(x, y, z, w);
        }
    }
}

// ---------------------------------------------------------------------------
// K2: edge scatter  out[dst] += norm * xr[etype, src]
// 16 threads per edge, one float4 + one red.global.add.v4.f32 each.
// ---------------------------------------------------------------------------
__global__ __launch_bounds__(256) void k2_scatter(const int* __restrict__ src,
                                                  const int* __restrict__ dst,
                                                  const int* __restrict__ etype,
                                                  const float* __restrict__ norm,
                                                  float* __restrict__ out,
                                                  int E, int N) {
    long long gid = (long long)blockIdx.x * 256 + threadIdx.x;
    int e = (int)(gid >> 4);
    if (e >= E) return;
    int q = ((int)gid & 15) * 4;

    int s   = __ldg(src + e);
    int d   = __ldg(dst + e);
    int r   = __ldg(etype + e);
    float nm = __ldg(norm + e);

    float4 v = *(const float4*)(g_xr + ((size_t)r * N + s) * D + q);
    float* p = out + (size_t)d * D + q;
    asm volatile("red.global.add.v4.f32 [%0], {%1,%2,%3,%4};"
                 :: "l"(p), "f"(v.x * nm), "f"(v.y * nm), "f"(v.z * nm), "f"(v.w * nm)
                 : "memory");
}

// ---------------------------------------------------------------------------
// K3: ReLU epilogue
// ---------------------------------------------------------------------------
__global__ void k3_relu(float* __restrict__ out, int total4) {
    int i = blockIdx.x * 256 + threadIdx.x;
    if (i < total4) {
        float4 v = ((float4*)out)[i];
        v.x = fmaxf(v.x, 0.f);
        v.y = fmaxf(v.y, 0.f);
        v.z = fmaxf(v.z, 0.f);
        v.w = fmaxf(v.w, 0.f);
        ((float4*)out)[i] = v;
    }
}

// ---------------------------------------------------------------------------
// Inputs (metadata order): feat, src, dst, etype, norm, weight, w_comp, self_loop_weight
// ---------------------------------------------------------------------------
extern "C" void kernel_launch(void* const* d_in, const int* in_sizes, int n_in,
                              void* d_out, int out_size) {
    const float* feat   = (const float*)d_in[0];
    const int*   src    = (const int*)  d_in[1];
    const int*   dst    = (const int*)  d_in[2];
    const int*   etype  = (const int*)  d_in[3];
    const float* norm   = (const float*)d_in[4];
    const float* weight = (const float*)d_in[5];
    const float* w_comp = (const float*)d_in[6];
    const float* self_w = (const float*)d_in[7];
    float*       out    = (float*)d_out;

    const int N = in_sizes[0] / D;
    const int E = in_sizes[1];
    const int B = in_sizes[5] / (D * D);
    const int R = in_sizes[6] / B;

    // K0: basis combine (tiny)
    k0_compute_W<<<R + 1, 256>>>(weight, w_comp, self_w, R, B);

    // K1: 11 GEMMs; r == R writes the self-loop term directly into d_out
    dim3 g1((N + 127) / 128, R + 1);
    k1_gemm<<<g1, 256>>>(feat, out, N, R);

    // K2: edge scatter-add into d_out
    long long items = (long long)E * 16;
    unsigned blocks2 = (unsigned)((items + 255) / 256);
    k2_scatter<<<blocks2, 256>>>(src, dst, etype, norm, out, E, N);

    // K3: ReLU
    int total4 = N * D / 4;
    k3_relu<<<(total4 + 255) / 256, 256>>>(out, total4);
}

// round 16
// speedup vs baseline: 1.5319x; 1.5319x over previous
#include <cuda_runtime.h>
#include <cuda_bf16.h>
#include <cstdint>

#define D 64
#define MAXN 50000
#define MAXR 10

// ---------------------------------------------------------------------------
// Scratch (__device__ globals: allocation-free rule)
// ---------------------------------------------------------------------------
__device__ __align__(16) float          g_xr[(size_t)MAXR * MAXN * D];   // [R,N,D] fp32
__device__ __align__(16) __nv_bfloat16  g_Bhi[(MAXR + 1) * D * D];       // W^T hi, [r][n][k]
__device__ __align__(16) __nv_bfloat16  g_Blo[(MAXR + 1) * D * D];       // W^T lo, [r][n][k]

// ---------------------------------------------------------------------------
// Helpers
// ---------------------------------------------------------------------------
__device__ __forceinline__ uint32_t smem_u32(const void* p) {
    uint32_t a;
    asm("{ .reg .u64 t; cvta.to.shared.u64 t, %1; cvt.u32.u64 %0, t; }" : "=r"(a) : "l"(p));
    return a;
}
__device__ __forceinline__ void ldsm_x4(uint32_t& r0, uint32_t& r1, uint32_t& r2, uint32_t& r3,
                                        uint32_t addr) {
    asm volatile("ldmatrix.sync.aligned.m8n8.x4.shared.b16 {%0,%1,%2,%3}, [%4];"
                 : "=r"(r0), "=r"(r1), "=r"(r2), "=r"(r3) : "r"(addr));
}
__device__ __forceinline__ void mma_bf16(float c[4], uint32_t a0, uint32_t a1, uint32_t a2,
                                         uint32_t a3, uint32_t b0, uint32_t b1) {
    asm volatile(
        "mma.sync.aligned.m16n8k16.row.col.f32.bf16.bf16.f32 "
        "{%0,%1,%2,%3},{%4,%5,%6,%7},{%8,%9},{%0,%1,%2,%3};"
        : "+f"(c[0]), "+f"(c[1]), "+f"(c[2]), "+f"(c[3])
        : "r"(a0), "r"(a1), "r"(a2), "r"(a3), "r"(b0), "r"(b1));
}

// ---------------------------------------------------------------------------
// K0: basis combine + transpose + hi/lo bf16 split.  g_B*[r][n][k] row-major.
// ---------------------------------------------------------------------------
__global__ void k0_prepW(const float* __restrict__ weight,
                         const float* __restrict__ w_comp,
                         const float* __restrict__ self_w,
                         int R, int B) {
    int r = blockIdx.x;
    for (int idx = threadIdx.x; idx < D * D; idx += blockDim.x) {
        int kk = idx >> 6, j = idx & 63;   // W[kk][j]
        float w;
        if (r < R) {
            w = 0.f;
            for (int b = 0; b < B; b++)
                w += w_comp[r * B + b] * weight[b * D * D + idx];
        } else {
            w = self_w[idx];
        }
        __nv_bfloat16 hi = __float2bfloat16(w);
        __nv_bfloat16 lo = __float2bfloat16(w - __bfloat162float(hi));
        g_Bhi[r * D * D + j * D + kk] = hi;   // row = n (=j), col = k (=kk)
        g_Blo[r * D * D + j * D + kk] = lo;
    }
}

// ---------------------------------------------------------------------------
// K1: HMMA (mma.sync bf16, hi/lo 3-pass) GEMM.
// Tile 128 nodes x 64 outs per block, 256 threads = 8 warps, warp = 16 rows.
// r < R -> g_xr ; r == R (self-loop) -> d_out (initializes it).
// SMEM rows padded to 144 B for conflict-free ldmatrix.
// ---------------------------------------------------------------------------
#define ROWB 144
#define SM_AHI 0
#define SM_ALO (128 * ROWB)            // 18432
#define SM_BHI (2 * 128 * ROWB)        // 36864
#define SM_BLO (2 * 128 * ROWB + 64 * ROWB)  // 46080
#define SM_TOTAL (2 * 128 * ROWB + 2 * 64 * ROWB)  // 55296

__global__ __launch_bounds__(256, 2)
void k1_mma(const float* __restrict__ feat, float* __restrict__ out, int N, int R) {
    extern __shared__ char smem[];
    const uint32_t sb = smem_u32(smem);
    const int t    = threadIdx.x;
    const int wid  = t >> 5, lid = t & 31;
    const int r    = blockIdx.y;
    const int base = blockIdx.x * 128;

    // ---- Fill B tiles: [64][64] bf16 -> padded smem rows ----
    {
        const uint4* bh = (const uint4*)(g_Bhi + (size_t)r * D * D);
        const uint4* bl = (const uint4*)(g_Blo + (size_t)r * D * D);
        #pragma unroll
        for (int i = 0; i < 2; i++) {
            int lin = t + i * 256;          // 0..511 uint4s (16B = 8 bf16)
            int row = lin >> 3, q = lin & 7;
            uint32_t doff = (uint32_t)row * ROWB + (uint32_t)q * 16;
            *(uint4*)(smem + SM_BHI + doff) = bh[lin];
            *(uint4*)(smem + SM_BLO + doff) = bl[lin];
        }
    }

    // ---- Fill A tiles: feat[base..base+127][0..63] -> bf16 hi/lo, padded ----
    #pragma unroll
    for (int i = 0; i < 8; i++) {
        int lin = t + i * 256;              // 0..2047 float4s
        int row = lin >> 4, c4 = lin & 15;
        int n = base + row;
        float4 v = make_float4(0.f, 0.f, 0.f, 0.f);
        if (n < N) v = *(const float4*)(feat + (size_t)n * D + c4 * 4);
        __nv_bfloat162 h01 = __floats2bfloat162_rn(v.x, v.y);
        __nv_bfloat162 h23 = __floats2bfloat162_rn(v.z, v.w);
        float lx = v.x - __bfloat162float(__low2bfloat16(h01));
        float ly = v.y - __bfloat162float(__high2bfloat16(h01));
        float lz = v.z - __bfloat162float(__low2bfloat16(h23));
        float lw = v.w - __bfloat162float(__high2bfloat16(h23));
        __nv_bfloat162 l01 = __floats2bfloat162_rn(lx, ly);
        __nv_bfloat162 l23 = __floats2bfloat162_rn(lz, lw);
        uint32_t doff = (uint32_t)row * ROWB + (uint32_t)c4 * 8;
        *(uint2*)(smem + SM_AHI + doff) = make_uint2(*(uint32_t*)&h01, *(uint32_t*)&h23);
        *(uint2*)(smem + SM_ALO + doff) = make_uint2(*(uint32_t*)&l01, *(uint32_t*)&l23);
    }
    __syncthreads();

    // ---- MMA mainloop ----
    const int m0 = wid * 16;
    float acc[8][4];
    #pragma unroll
    for (int i = 0; i < 8; i++)
        #pragma unroll
        for (int j = 0; j < 4; j++) acc[i][j] = 0.f;

    // A lane addr: row = m0 + (lid&15), koff16B = (lid>>4)
    const uint32_t a_lane = sb + (uint32_t)(m0 + (lid & 15)) * ROWB + ((lid >> 4) * 16);
    // B lane addr (per pair p): row = p*16 + (lid&7) + ((lid>>4)&1)*8, koff16B = (lid>>3)&1
    const uint32_t b_row  = (uint32_t)((lid & 7) + ((lid >> 4) & 1) * 8);
    const uint32_t b_lane = sb + SM_BHI + b_row * ROWB + (((lid >> 3) & 1) * 16);

    #pragma unroll
    for (int kc = 0; kc < 4; kc++) {
        uint32_t ah0, ah1, ah2, ah3, al0, al1, al2, al3;
        ldsm_x4(ah0, ah1, ah2, ah3, a_lane + SM_AHI + kc * 32);
        ldsm_x4(al0, al1, al2, al3, a_lane + SM_ALO + kc * 32);
        #pragma unroll
        for (int p = 0; p < 4; p++) {
            uint32_t bh0, bh1, bh2, bh3, bl0, bl1, bl2, bl3;
            uint32_t ba = b_lane + (uint32_t)p * 16 * ROWB + kc * 32;
            ldsm_x4(bh0, bh1, bh2, bh3, ba);
            ldsm_x4(bl0, bl1, bl2, bl3, ba + (SM_BLO - SM_BHI));
            mma_bf16(acc[2 * p],     ah0, ah1, ah2, ah3, bh0, bh1);
            mma_bf16(acc[2 * p],     ah0, ah1, ah2, ah3, bl0, bl1);
            mma_bf16(acc[2 * p],     al0, al1, al2, al3, bh0, bh1);
            mma_bf16(acc[2 * p + 1], ah0, ah1, ah2, ah3, bh2, bh3);
            mma_bf16(acc[2 * p + 1], ah0, ah1, ah2, ah3, bl2, bl3);
            mma_bf16(acc[2 * p + 1], al0, al1, al2, al3, bh2, bh3);
        }
    }

    // ---- Epilogue: direct STG.64 from accumulators ----
    float* dstbase = (r < R) ? (g_xr + (size_t)r * N * D) : out;
    int row0 = base + m0 + (lid >> 2);
    int col  = (lid & 3) * 2;
    #pragma unroll
    for (int nt = 0; nt < 8; nt++) {
        if (row0 < N)
            *(float2*)(dstbase + (size_t)row0 * D + nt * 8 + col) =
                make_float2(acc[nt][0], acc[nt][1]);
        if (row0 + 8 < N)
            *(float2*)(dstbase + (size_t)(row0 + 8) * D + nt * 8 + col) =
                make_float2(acc[nt][2], acc[nt][3]);
    }
}

// ---------------------------------------------------------------------------
// K2: edge scatter  out[dst] += norm * g_xr[etype, src]
// ---------------------------------------------------------------------------
__global__ __launch_bounds__(256) void k2_scatter(const int* __restrict__ src,
                                                  const int* __restrict__ dst,
                                                  const int* __restrict__ etype,
                                                  const float* __restrict__ norm,
                                                  float* __restrict__ out,
                                                  int E, int N) {
    long long gid = (long long)blockIdx.x * 256 + threadIdx.x;
    int e = (int)(gid >> 4);
    if (e >= E) return;
    int q = ((int)gid & 15) * 4;

    int s    = __ldg(src + e);
    int d    = __ldg(dst + e);
    int r    = __ldg(etype + e);
    float nm = __ldg(norm + e);

    float4 v = *(const float4*)(g_xr + ((size_t)r * N + s) * D + q);
    float* p = out + (size_t)d * D + q;
    asm volatile("red.global.add.v4.f32 [%0], {%1,%2,%3,%4};"
                 :: "l"(p), "f"(v.x * nm), "f"(v.y * nm), "f"(v.z * nm), "f"(v.w * nm)
                 : "memory");
}

// ---------------------------------------------------------------------------
// K3: ReLU epilogue
// ---------------------------------------------------------------------------
__global__ void k3_relu(float* __restrict__ out, int total4) {
    int i = blockIdx.x * 256 + threadIdx.x;
    if (i < total4) {
        float4 v = ((float4*)out)[i];
        v.x = fmaxf(v.x, 0.f);
        v.y = fmaxf(v.y, 0.f);
        v.z = fmaxf(v.z, 0.f);
        v.w = fmaxf(v.w, 0.f);
        ((float4*)out)[i] = v;
    }
}

// ---------------------------------------------------------------------------
// Inputs: feat, src, dst, etype, norm, weight, w_comp, self_loop_weight
// ---------------------------------------------------------------------------
extern "C" void kernel_launch(void* const* d_in, const int* in_sizes, int n_in,
                              void* d_out, int out_size) {
    const float* feat   = (const float*)d_in[0];
    const int*   src    = (const int*)  d_in[1];
    const int*   dst    = (const int*)  d_in[2];
    const int*   etype  = (const int*)  d_in[3];
    const float* norm   = (const float*)d_in[4];
    const float* weight = (const float*)d_in[5];
    const float* w_comp = (const float*)d_in[6];
    const float* self_w = (const float*)d_in[7];
    float*       out    = (float*)d_out;

    const int N = in_sizes[0] / D;
    const int E = in_sizes[1];
    const int B = in_sizes[5] / (D * D);
    const int R = in_sizes[6] / B;

    cudaFuncSetAttribute(k1_mma, cudaFuncAttributeMaxDynamicSharedMemorySize, SM_TOTAL);

    // K0: basis combine + transpose + bf16 hi/lo split
    k0_prepW<<<R + 1, 256>>>(weight, w_comp, self_w, R, B);

    // K1: 11 HMMA GEMMs; r == R writes self-loop directly into d_out
    dim3 g1((N + 127) / 128, R + 1);
    k1_mma<<<g1, 256, SM_TOTAL>>>(feat, out, N, R);

    // K2: edge scatter-add
    long long items = (long long)E * 16;
    unsigned blocks2 = (unsigned)((items + 255) / 256);
    k2_scatter<<<blocks2, 256>>>(src, dst, etype, norm, out, E, N);

    // K3: ReLU
    int total4 = N * D / 4;
    k3_relu<<<(total4 + 255) / 256, 256>>>(out, total4);
}